// round 14
// baseline (speedup 1.0000x reference)
#include <cuda_runtime.h>
#include <cuda_fp16.h>
#include <cstdint>

// B=8, N=2048, F=D=128
//   H = A_hat@X ; O = H@W^T + b ; out = relu(LN(O)*gamma+beta)
// Re-associated:  Y = X@W^T (tiny) ;  O = A_hat@Y  ->  fused LN+ReLU epilogue.
//
// R13 = R12 (fp16 m16n8k16 path) + latency fixes:
//  - A LDG double-buffered in regs: issue at cc-4, convert+STS at cc-2
//    (2 iterations of slack), placed AFTER the chunk's MMA work.
//  - 3 CTAs/SM (smem 64KB/CTA): 3 warps/SMSP. Fragment single-buffered to fit
//    the 168-reg cap at occupancy 3.

#define BATCH 8
#define NN    2048
#define FF    128
#define ROWS  64
#define CK    32
#define NCH   64
#define PADH2 40             // stage pitch in halves (80 B rows)
#define PADW  132            // y_kernel fp32 tile pitch

#define ST_Y_OFF  5120       // A part: 64*40*2
#define STAGE_B   15360      // + Y part: 128*40*2 = 10240
#define SM_MBAR   61440      // full[4]@+0, empty[4]@+32
#define SM_PAR    61504      // bias|gamma|beta 3*512
#define SM_RED    63040      // 64 rows x 2 x {s1,s2} = 1024
#define SM_TOTAL  64064      // x3 CTAs = 192192 <= 227KB

#define SM_Y_TOTAL 135168    // y_kernel: W 128*132*4 + X 128*132*4

__device__ __align__(16) __half g_Yth[BATCH * FF * NN];   // 4 MB scratch

__device__ __forceinline__ uint32_t smem_u32(const void* p) {
    uint32_t a;
    asm("{ .reg .u64 t; cvta.to.shared.u64 t, %1; cvt.u32.u64 %0, t; }" : "=r"(a) : "l"(p));
    return a;
}
__device__ __forceinline__ void cp16(uint32_t dst, const void* src) {
    asm volatile("cp.async.cg.shared.global [%0], [%1], 16;" :: "r"(dst), "l"(src) : "memory");
}
__device__ __forceinline__ uint32_t f16x2(float lo, float hi) {
    uint32_t r;
    asm("cvt.rn.f16x2.f32 %0, %1, %2;" : "=r"(r) : "f"(hi), "f"(lo));
    return r;
}

#define MBAR_INIT(mb, c)  asm volatile("mbarrier.init.shared.b64 [%0], %1;" :: "r"(mb), "r"(c) : "memory")
#define MBAR_ARRIVE(mb)   asm volatile("mbarrier.arrive.shared.b64 _, [%0];" :: "r"(mb) : "memory")
#define CP_ARRIVE(mb)     asm volatile("cp.async.mbarrier.arrive.noinc.shared::cta.b64 [%0];" :: "r"(mb) : "memory")

#define MBAR_WAIT(mb, ph) do {                                                     \
    uint32_t _m = (mb); uint32_t _p = (ph); uint32_t _d;                           \
    asm volatile("{\n\t.reg .pred p;\n\t"                                          \
        "mbarrier.try_wait.parity.acquire.cta.shared::cta.b64 p, [%1], %2;\n\t"    \
        "selp.b32 %0, 1, 0, p;\n\t}" : "=r"(_d) : "r"(_m), "r"(_p) : "memory");    \
    if (!_d) {                                                                     \
        asm volatile("{\n\t.reg .pred P1;\n\t"                                     \
        "W_%=:\n\t"                                                                \
        "mbarrier.try_wait.parity.acquire.cta.shared::cta.b64 P1, [%0], %1, 0x989680;\n\t" \
        "@P1 bra.uni D_%=;\n\tbra.uni W_%=;\n\tD_%=:\n\t}"                         \
        :: "r"(_m), "r"(_p) : "memory");                                           \
    }                                                                              \
} while (0)

#define LDSM_X4(r0, r1, r2, r3, addr)                                           \
    asm volatile("ldmatrix.sync.aligned.m8n8.x4.shared.b16 {%0,%1,%2,%3}, [%4];"\
        : "=r"(r0), "=r"(r1), "=r"(r2), "=r"(r3) : "r"(addr))

#define MMA_TF32(d, av, bv)                                                     \
    asm volatile("mma.sync.aligned.m16n8k8.row.col.f32.tf32.tf32.f32 "          \
        "{%0,%1,%2,%3}, {%4,%5,%6,%7}, {%8,%9}, {%0,%1,%2,%3};"                 \
        : "+f"((d)[0]), "+f"((d)[1]), "+f"((d)[2]), "+f"((d)[3])                \
        : "r"((av)[0]), "r"((av)[1]), "r"((av)[2]), "r"((av)[3]),               \
          "r"((bv)[0]), "r"((bv)[1]))

#define MMA_F16(d, av, bv)                                                      \
    asm volatile("mma.sync.aligned.m16n8k16.row.col.f32.f16.f16.f32 "           \
        "{%0,%1,%2,%3}, {%4,%5,%6,%7}, {%8,%9}, {%0,%1,%2,%3};"                 \
        : "+f"((d)[0]), "+f"((d)[1]), "+f"((d)[2]), "+f"((d)[3])                \
        : "r"((av)[0]), "r"((av)[1]), "r"((av)[2]), "r"((av)[3]),               \
          "r"((bv)[0]), "r"((bv)[1]))

// ---------------- k0: Yt[b][d][n] (fp16) = sum_f X[b][n][f] * W[d][f] ----------------
__global__ __launch_bounds__(256, 1)
void y_kernel(const float* __restrict__ X, const float* __restrict__ W) {
    extern __shared__ char ysm[];
    float* sW = (float*)ysm;                         // [128][132]
    float* sX = (float*)(ysm + 67584);               // [128][132]
    const uint32_t wU = smem_u32(sW);
    const uint32_t xU = smem_u32(sX);

    const int tid = threadIdx.x;
    const int lid = tid & 31;
    const int wid = tid >> 5;
    const int wm  = wid >> 1, wn = wid & 1;
    const int gp  = lid >> 2, tg = lid & 3;
    const int s   = lid >> 3, rr = lid & 7;
    const int aR = (s & 1) * 8 + rr, aC = (s >> 1) * 4;
    const int bR = (s >> 1) * 8 + rr, bC = (s & 1) * 4;

    const int n0 = blockIdx.x * 128;
    const int bt = blockIdx.y;
    const float* Xb = X + (size_t)bt * NN * FF + (size_t)n0 * FF;

#pragma unroll
    for (int i = 0; i < 16; i++) {
        int id = tid + i * 256;
        int r = id >> 5, q = id & 31;
        *(float4*)(sW + r * PADW + q * 4) = *(const float4*)(W  + (size_t)r * FF + q * 4);
        *(float4*)(sX + r * PADW + q * 4) = *(const float4*)(Xb + (size_t)r * FF + q * 4);
    }
    __syncthreads();

    float acc[2][8][4];
#pragma unroll
    for (int i = 0; i < 2; i++)
#pragma unroll
        for (int j = 0; j < 8; j++)
#pragma unroll
            for (int k = 0; k < 4; k++) acc[i][j][k] = 0.f;

#pragma unroll
    for (int k8 = 0; k8 < 16; k8++) {
        const int kb = k8 * 8;
        uint32_t af[2][4], bf[8][2];
#pragma unroll
        for (int mt = 0; mt < 2; mt++) {
            uint32_t ad = wU + (uint32_t)((wm * 32 + mt * 16 + aR) * PADW + kb + aC) * 4u;
            LDSM_X4(af[mt][0], af[mt][1], af[mt][2], af[mt][3], ad);
        }
#pragma unroll
        for (int p = 0; p < 4; p++) {
            uint32_t bd = xU + (uint32_t)((wn * 64 + p * 16 + bR) * PADW + kb + bC) * 4u;
            LDSM_X4(bf[p * 2][0], bf[p * 2][1], bf[p * 2 + 1][0], bf[p * 2 + 1][1], bd);
        }
#pragma unroll
        for (int mt = 0; mt < 2; mt++)
#pragma unroll
            for (int nt = 0; nt < 8; nt++)
                MMA_TF32(acc[mt][nt], af[mt], bf[nt]);
    }

    __half* Yb = g_Yth + (size_t)bt * FF * NN;
#pragma unroll
    for (int mt = 0; mt < 2; mt++)
#pragma unroll
        for (int h = 0; h < 2; h++) {
            int d = wm * 32 + mt * 16 + h * 8 + gp;
#pragma unroll
            for (int nt = 0; nt < 8; nt++) {
                int n = n0 + wn * 64 + nt * 8 + 2 * tg;
                *(__half2*)(Yb + (size_t)d * NN + n) =
                    __floats2half2_rn(acc[mt][nt][h * 2 + 0], acc[mt][nt][h * 2 + 1]);
            }
        }
}

// ---------------- k1: fused O = A@Yt (fp16 MMA) -> bias+LN+ReLU ----------------
__global__ __launch_bounds__(128, 3)
void fused_kernel(const float* __restrict__ A,
                  const float* __restrict__ bias, const float* __restrict__ gamma,
                  const float* __restrict__ beta, float* __restrict__ out) {
    extern __shared__ char smem[];
    float* sf = (float*)smem;
    const uint32_t sbu = smem_u32(smem);

    const int tid = threadIdx.x;
    const int lid = tid & 31;
    const int wid = tid >> 5;           // 0..3
    const int wm  = wid >> 1;           // rows half
    const int wn  = wid & 1;            // cols half
    const int gp  = lid >> 2, tg = lid & 3;
    const int s   = lid >> 3, rr = lid & 7;
    // fp16 frag addressing (units: halves)
    const int aR = (s & 1) * 8 + rr, aC = (s >> 1) * 8;
    const int bR = (s >> 1) * 8 + rr, bC = (s & 1) * 8;

    const int bt      = blockIdx.x >> 5;
    const int rowTile = blockIdx.x & 31;
    const float*  Ab = A     + (size_t)bt * NN * NN + (size_t)rowTile * ROWS * NN;
    const __half* Yb = g_Yth + (size_t)bt * FF * NN;

    // full[st]: 128 Y cp.async-arrives + 128 A STS thread-arrives = 256
    if (tid == 0) {
#pragma unroll
        for (int st = 0; st < 4; st++) {
            MBAR_INIT(sbu + SM_MBAR + st * 8, 256);
            MBAR_INIT(sbu + SM_MBAR + 32 + st * 8, 4);
        }
    }
    sf[SM_PAR / 4 + tid]       = bias[tid];
    sf[SM_PAR / 4 + 128 + tid] = gamma[tid];
    sf[SM_PAR / 4 + 256 + tid] = beta[tid];
    __syncthreads();

    float acc[2][8][4];
#pragma unroll
    for (int i = 0; i < 2; i++)
#pragma unroll
        for (int j = 0; j < 8; j++)
#pragma unroll
            for (int k = 0; k < 4; k++) acc[i][j][k] = 0.f;

    float4 areg[2][4];                   // 2-deep A register pipeline

    auto ldgA = [&](int c, int b) {      // coalesced: 8 lanes cover one 128B row
        const float* ga = Ab + c * CK;
#pragma unroll
        for (int i = 0; i < 4; i++) {
            int id = tid + i * 128;
            int r = id >> 3, q = id & 7;
            areg[b][i] = *(const float4*)(ga + (size_t)r * NN + q * 4);
        }
    };
    auto cvtsts = [&](int cc) {          // convert buf (cc&1) -> fp16 stage; arm full
        const uint32_t ab = sbu + (uint32_t)(cc & 3) * STAGE_B;
        const int b = cc & 1;
#pragma unroll
        for (int i = 0; i < 4; i++) {
            int id = tid + i * 128;
            int r = id >> 3, q = id & 7;
            uint32_t h01 = f16x2(areg[b][i].x, areg[b][i].y);
            uint32_t h23 = f16x2(areg[b][i].z, areg[b][i].w);
            asm volatile("st.shared.v2.b32 [%0], {%1, %2};"
                :: "r"(ab + (uint32_t)(r * 80 + q * 8)), "r"(h01), "r"(h23) : "memory");
        }
        MBAR_ARRIVE(sbu + SM_MBAR + (cc & 3) * 8);
    };
    auto ycp = [&](int c) {              // Y fp16 via cp.async; arm full on completion
        const uint32_t yb = sbu + (uint32_t)(c & 3) * STAGE_B + ST_Y_OFF;
        const __half* gy = Yb + c * CK;
#pragma unroll
        for (int i = 0; i < 4; i++) {
            int id = tid + i * 128;
            int r = id >> 2, q = id & 3;
            cp16(yb + (uint32_t)(r * 80 + q * 16), gy + (size_t)r * NN + q * 8);
        }
        CP_ARRIVE(sbu + SM_MBAR + (c & 3) * 8);
    };

    // ---- prologue: mirror steady state at c=0 ----
    // staged fully: chunks 0,1 (A cvt'd + Y);  Y in flight: chunk 2;
    // A pending in regs: chunks 2 (buf0), 3 (buf1)
    ldgA(0, 0); ycp(0);
    ldgA(1, 1); ycp(1);
    cvtsts(0);                // consumes buf0
    ldgA(2, 0); ycp(2);
    cvtsts(1);                // consumes buf1
    ldgA(3, 1);

    uint32_t af[2][4], bf[8][2];         // single-buffered fragments

    auto ldA = [&](uint32_t base, int kb) {
#pragma unroll
        for (int mt = 0; mt < 2; mt++) {
            uint32_t ad = base + (uint32_t)((wm * 32 + mt * 16 + aR) * PADH2 + kb + aC) * 2u;
            LDSM_X4(af[mt][0], af[mt][1], af[mt][2], af[mt][3], ad);
        }
    };
    auto ldB = [&](uint32_t base, int kb) {
#pragma unroll
        for (int p = 0; p < 4; p++) {
            uint32_t bd = base + (uint32_t)((wn * 64 + p * 16 + bR) * PADH2 + kb + bC) * 2u;
            LDSM_X4(bf[p * 2][0], bf[p * 2][1],
                    bf[p * 2 + 1][0], bf[p * 2 + 1][1], bd);
        }
    };

    for (int c = 0; c < NCH; c++) {
        const int st = c & 3;
        // issue chunk c+3's Y loads (stage drained via empty barrier)
        if (c + 3 < NCH) {
            const int cc = c + 3, st3 = cc & 3;
            if (cc >= 4) MBAR_WAIT(sbu + SM_MBAR + 32 + st3 * 8, ((cc >> 2) - 1) & 1);
            ycp(cc);
        }
        // consume chunk c
        MBAR_WAIT(sbu + SM_MBAR + st * 8, (c >> 2) & 1);
        const uint32_t aBase = sbu + (uint32_t)st * STAGE_B;
        const uint32_t yBase = aBase + ST_Y_OFF;
#pragma unroll
        for (int k16 = 0; k16 < 2; k16++) {
            ldA(aBase, k16 * 16);
            ldB(yBase, k16 * 16);
#pragma unroll
            for (int mt = 0; mt < 2; mt++)
#pragma unroll
                for (int nt = 0; nt < 8; nt++)
                    MMA_F16(acc[mt][nt], af[mt], bf[nt]);
        }
        if (lid == 0) MBAR_ARRIVE(sbu + SM_MBAR + 32 + st * 8);
        // stage chunk c+2's A (LDG issued 2 iterations ago -> latency hidden),
        // then refill the freed reg buffer with chunk c+4's A
        if (c + 2 < NCH) cvtsts(c + 2);
        if (c + 4 < NCH) ldgA(c + 4, c & 1);
    }

    // ---- epilogue: bias + LayerNorm + ReLU ----
    const float* sbias = sf + SM_PAR / 4;
    const float* sgam  = sbias + 128;
    const float* sbet  = sbias + 256;
    float* sred = sf + SM_RED / 4;

    float s1[2][2], s2[2][2];
#pragma unroll
    for (int mt = 0; mt < 2; mt++) { s1[mt][0] = s1[mt][1] = s2[mt][0] = s2[mt][1] = 0.f; }
#pragma unroll
    for (int mt = 0; mt < 2; mt++)
#pragma unroll
        for (int nt = 0; nt < 8; nt++) {
            int cc = wn * 64 + nt * 8 + 2 * tg;
            float b0 = sbias[cc], b1 = sbias[cc + 1];
            float v0 = acc[mt][nt][0] + b0, v1 = acc[mt][nt][1] + b1;
            float v2 = acc[mt][nt][2] + b0, v3 = acc[mt][nt][3] + b1;
            acc[mt][nt][0] = v0; acc[mt][nt][1] = v1;
            acc[mt][nt][2] = v2; acc[mt][nt][3] = v3;
            s1[mt][0] += v0 + v1;           s2[mt][0] += v0 * v0 + v1 * v1;
            s1[mt][1] += v2 + v3;           s2[mt][1] += v2 * v2 + v3 * v3;
        }
#pragma unroll
    for (int mt = 0; mt < 2; mt++)
#pragma unroll
        for (int h = 0; h < 2; h++) {
            s1[mt][h] += __shfl_xor_sync(0xffffffffu, s1[mt][h], 1);
            s1[mt][h] += __shfl_xor_sync(0xffffffffu, s1[mt][h], 2);
            s2[mt][h] += __shfl_xor_sync(0xffffffffu, s2[mt][h], 1);
            s2[mt][h] += __shfl_xor_sync(0xffffffffu, s2[mt][h], 2);
        }
    if (tg == 0) {
#pragma unroll
        for (int mt = 0; mt < 2; mt++)
#pragma unroll
            for (int h = 0; h < 2; h++) {
                int r = wm * 32 + mt * 16 + h * 8 + gp;
                sred[r * 4 + wn * 2 + 0] = s1[mt][h];
                sred[r * 4 + wn * 2 + 1] = s2[mt][h];
            }
    }
    __syncthreads();

    float* outBase = out + ((size_t)bt * NN + (size_t)rowTile * ROWS) * FF;
#pragma unroll
    for (int mt = 0; mt < 2; mt++)
#pragma unroll
        for (int h = 0; h < 2; h++) {
            int r = wm * 32 + mt * 16 + h * 8 + gp;
            float S1 = sred[r * 4 + 0] + sred[r * 4 + 2];
            float S2 = sred[r * 4 + 1] + sred[r * 4 + 3];
            float mean = S1 * (1.0f / 128.0f);
            float var  = S2 * (1.0f / 128.0f) - mean * mean;
            float inv  = rsqrtf(var + 1e-5f);
            float* orow = outBase + (size_t)r * FF;
#pragma unroll
            for (int nt = 0; nt < 8; nt++) {
                int cc = wn * 64 + nt * 8 + 2 * tg;
                float v0 = acc[mt][nt][h * 2 + 0];
                float v1 = acc[mt][nt][h * 2 + 1];
                float o0 = fmaxf((v0 - mean) * inv * sgam[cc]     + sbet[cc],     0.f);
                float o1 = fmaxf((v1 - mean) * inv * sgam[cc + 1] + sbet[cc + 1], 0.f);
                *(float2*)(orow + cc) = make_float2(o0, o1);
            }
        }
}

// ---------------- launch ----------------
extern "C" void kernel_launch(void* const* d_in, const int* in_sizes, int n_in,
                              void* d_out, int out_size) {
    const float* A     = (const float*)d_in[0];   // [8,2048,2048]
    const float* X     = (const float*)d_in[1];   // [8,2048,128]
    const float* W     = (const float*)d_in[2];   // [128,128]
    const float* bias  = (const float*)d_in[3];
    const float* gamma = (const float*)d_in[4];
    const float* beta  = (const float*)d_in[5];
    float* out = (float*)d_out;

    cudaFuncSetAttribute(y_kernel, cudaFuncAttributeMaxDynamicSharedMemorySize, SM_Y_TOTAL);
    cudaFuncSetAttribute(fused_kernel, cudaFuncAttributeMaxDynamicSharedMemorySize, SM_TOTAL);

    y_kernel<<<dim3(16, 8), 256, SM_Y_TOTAL>>>(X, W);
    fused_kernel<<<BATCH * (NN / ROWS), 128, SM_TOTAL>>>(A, bias, gamma, beta, out);
}

// round 15
// speedup vs baseline: 1.4925x; 1.4925x over previous
#include <cuda_runtime.h>
#include <cstdint>

// B=8, N=2048, F=D=128
//   H = A_hat@X ; O = H@W^T + b ; out = relu(LN(O)*gamma+beta)
// Re-associated:  Y = X@W^T (tiny) ;  O = A_hat@Y  ->  fused LN+ReLU epilogue.
//
// R14 = R10 (best, 63.6us: tf32 m16n8k8, integrated 4-warp CTA, 4-stage
// mbarrier ring) + decoupled loop order: consume-first, prefetch mid-chunk.
// The empty-barrier wait (which requires ALL warps to have finished chunk c-1)
// now sits AFTER half of this warp's chunk-c MMA work instead of before any
// of it, so inter-warp coupling overlaps with compute.

#define BATCH 8
#define NN    2048
#define FF    128
#define ROWS  64
#define CK    32
#define NCH   64
#define PADA  36             // stage pitch (36 % 32 == 4 -> LDSM conflict-free)
#define PADW  132            // y_kernel tile pitch

#define ST_Y_OFF  9216       // A part 64*36*4
#define STAGE_B   27648      // + Y part 128*36*4 = 18432
#define SM_MBAR   110592     // full[4] @ +0, empty[4] @ +32
#define SM_PAR    110656     // bias|gamma|beta 3*512
#define SM_RED    112192     // 64 rows x 2 x {s1,s2} = 1024
#define SM_TOTAL  113216     // x2 CTAs = 226432

#define SM_Y_TOTAL 135168    // y_kernel: W 128*132*4 + X 128*132*4

__device__ __align__(16) float g_Yt[BATCH * FF * NN];   // 8 MB scratch

__device__ __forceinline__ uint32_t smem_u32(const void* p) {
    uint32_t a;
    asm("{ .reg .u64 t; cvta.to.shared.u64 t, %1; cvt.u32.u64 %0, t; }" : "=r"(a) : "l"(p));
    return a;
}
__device__ __forceinline__ void cp16(uint32_t dst, const void* src) {
    asm volatile("cp.async.cg.shared.global [%0], [%1], 16;" :: "r"(dst), "l"(src) : "memory");
}

#define MBAR_INIT(mb, c)  asm volatile("mbarrier.init.shared.b64 [%0], %1;" :: "r"(mb), "r"(c) : "memory")
#define MBAR_ARRIVE(mb)   asm volatile("mbarrier.arrive.shared.b64 _, [%0];" :: "r"(mb) : "memory")
#define CP_ARRIVE(mb)     asm volatile("cp.async.mbarrier.arrive.noinc.shared::cta.b64 [%0];" :: "r"(mb) : "memory")

#define MBAR_WAIT(mb, ph) do {                                                     \
    uint32_t _m = (mb); uint32_t _p = (ph); uint32_t _d;                           \
    asm volatile("{\n\t.reg .pred p;\n\t"                                          \
        "mbarrier.try_wait.parity.acquire.cta.shared::cta.b64 p, [%1], %2;\n\t"    \
        "selp.b32 %0, 1, 0, p;\n\t}" : "=r"(_d) : "r"(_m), "r"(_p) : "memory");    \
    if (!_d) {                                                                     \
        asm volatile("{\n\t.reg .pred P1;\n\t"                                     \
        "W_%=:\n\t"                                                                \
        "mbarrier.try_wait.parity.acquire.cta.shared::cta.b64 P1, [%0], %1, 0x989680;\n\t" \
        "@P1 bra.uni D_%=;\n\tbra.uni W_%=;\n\tD_%=:\n\t}"                         \
        :: "r"(_m), "r"(_p) : "memory");                                           \
    }                                                                              \
} while (0)

#define LDSM_X4(r0, r1, r2, r3, addr)                                           \
    asm volatile("ldmatrix.sync.aligned.m8n8.x4.shared.b16 {%0,%1,%2,%3}, [%4];"\
        : "=r"(r0), "=r"(r1), "=r"(r2), "=r"(r3) : "r"(addr))

#define MMA_TF32(d, av, bv)                                                     \
    asm volatile("mma.sync.aligned.m16n8k8.row.col.f32.tf32.tf32.f32 "          \
        "{%0,%1,%2,%3}, {%4,%5,%6,%7}, {%8,%9}, {%0,%1,%2,%3};"                 \
        : "+f"((d)[0]), "+f"((d)[1]), "+f"((d)[2]), "+f"((d)[3])                \
        : "r"((av)[0]), "r"((av)[1]), "r"((av)[2]), "r"((av)[3]),               \
          "r"((bv)[0]), "r"((bv)[1]))

// ---------------- k0: Yt[b][d][n] = sum_f X[b][n][f] * W[d][f] ----------------
__global__ __launch_bounds__(256, 1)
void y_kernel(const float* __restrict__ X, const float* __restrict__ W) {
    extern __shared__ char ysm[];
    float* sW = (float*)ysm;                         // [128][132]
    float* sX = (float*)(ysm + 67584);               // [128][132]
    const uint32_t wU = smem_u32(sW);
    const uint32_t xU = smem_u32(sX);

    const int tid = threadIdx.x;
    const int lid = tid & 31;
    const int wid = tid >> 5;
    const int wm  = wid >> 1, wn = wid & 1;
    const int gp  = lid >> 2, tg = lid & 3;
    const int s   = lid >> 3, rr = lid & 7;
    const int aR = (s & 1) * 8 + rr, aC = (s >> 1) * 4;
    const int bR = (s >> 1) * 8 + rr, bC = (s & 1) * 4;

    const int n0 = blockIdx.x * 128;
    const int bt = blockIdx.y;
    const float* Xb = X + (size_t)bt * NN * FF + (size_t)n0 * FF;

#pragma unroll
    for (int i = 0; i < 16; i++) {
        int id = tid + i * 256;
        int r = id >> 5, q = id & 31;
        *(float4*)(sW + r * PADW + q * 4) = *(const float4*)(W  + (size_t)r * FF + q * 4);
        *(float4*)(sX + r * PADW + q * 4) = *(const float4*)(Xb + (size_t)r * FF + q * 4);
    }
    __syncthreads();

    float acc[2][8][4];
#pragma unroll
    for (int i = 0; i < 2; i++)
#pragma unroll
        for (int j = 0; j < 8; j++)
#pragma unroll
            for (int k = 0; k < 4; k++) acc[i][j][k] = 0.f;

#pragma unroll
    for (int k8 = 0; k8 < 16; k8++) {
        const int kb = k8 * 8;
        uint32_t af[2][4], bf[8][2];
#pragma unroll
        for (int mt = 0; mt < 2; mt++) {
            uint32_t ad = wU + (uint32_t)((wm * 32 + mt * 16 + aR) * PADW + kb + aC) * 4u;
            LDSM_X4(af[mt][0], af[mt][1], af[mt][2], af[mt][3], ad);
        }
#pragma unroll
        for (int p = 0; p < 4; p++) {
            uint32_t bd = xU + (uint32_t)((wn * 64 + p * 16 + bR) * PADW + kb + bC) * 4u;
            LDSM_X4(bf[p * 2][0], bf[p * 2][1], bf[p * 2 + 1][0], bf[p * 2 + 1][1], bd);
        }
#pragma unroll
        for (int mt = 0; mt < 2; mt++)
#pragma unroll
            for (int nt = 0; nt < 8; nt++)
                MMA_TF32(acc[mt][nt], af[mt], bf[nt]);
    }

    float* Yb = g_Yt + (size_t)bt * FF * NN;
#pragma unroll
    for (int mt = 0; mt < 2; mt++)
#pragma unroll
        for (int h = 0; h < 2; h++) {
            int d = wm * 32 + mt * 16 + h * 8 + gp;
#pragma unroll
            for (int nt = 0; nt < 8; nt++) {
                int n = n0 + wn * 64 + nt * 8 + 2 * tg;
                *(float2*)(Yb + (size_t)d * NN + n) =
                    make_float2(acc[mt][nt][h * 2 + 0], acc[mt][nt][h * 2 + 1]);
            }
        }
}

// ---------------- k1: fused O = A@Yt -> bias+LN+ReLU ----------------
__global__ __launch_bounds__(128, 2)
void fused_kernel(const float* __restrict__ A,
                  const float* __restrict__ bias, const float* __restrict__ gamma,
                  const float* __restrict__ beta, float* __restrict__ out) {
    extern __shared__ char smem[];
    float* sf = (float*)smem;
    const uint32_t sbu = smem_u32(smem);

    const int tid = threadIdx.x;
    const int lid = tid & 31;
    const int wid = tid >> 5;           // 0..3
    const int wm  = wid >> 1;           // rows half
    const int wn  = wid & 1;            // cols half
    const int gp  = lid >> 2, tg = lid & 3;
    const int s   = lid >> 3, rr = lid & 7;
    const int aR = (s & 1) * 8 + rr, aC = (s >> 1) * 4;
    const int bR = (s >> 1) * 8 + rr, bC = (s & 1) * 4;

    const int bt      = blockIdx.x >> 5;
    const int rowTile = blockIdx.x & 31;
    const float* Ab = A    + (size_t)bt * NN * NN + (size_t)rowTile * ROWS * NN;
    const float* Yb = g_Yt + (size_t)bt * FF * NN;

    if (tid == 0) {
#pragma unroll
        for (int st = 0; st < 4; st++) {
            MBAR_INIT(sbu + SM_MBAR + st * 8, 128);     // full: cp.async arrivals
            MBAR_INIT(sbu + SM_MBAR + 32 + st * 8, 4);  // empty: 4 warp arrivals
        }
    }
    sf[SM_PAR / 4 + tid]       = bias[tid];
    sf[SM_PAR / 4 + 128 + tid] = gamma[tid];
    sf[SM_PAR / 4 + 256 + tid] = beta[tid];
    __syncthreads();

    float acc[2][8][4];
#pragma unroll
    for (int i = 0; i < 2; i++)
#pragma unroll
        for (int j = 0; j < 8; j++)
#pragma unroll
            for (int k = 0; k < 4; k++) acc[i][j][k] = 0.f;

    // each warp loads its slice of the stage, interleaving A and Y rows;
    // full[st] arms when all 128 threads' cp.asyncs complete
    auto load_chunk = [&](int c) {
        const int st = c & 3;
        const uint32_t ab = sbu + (uint32_t)st * STAGE_B;
        const uint32_t yb = ab + ST_Y_OFF;
        const float* ga = Ab + c * CK;
        const float* gy = Yb + c * CK;
#pragma unroll
        for (int i = 0; i < 4; i++) {
            // A row (64 rows total)
            int ia = wid * 128 + lid + i * 32;
            int ra = ia >> 3, qa = ia & 7;
            cp16(ab + (uint32_t)(ra * PADA + qa * 4) * 4u, ga + (size_t)ra * NN + qa * 4);
            // 2 Y rows (128 rows total)
#pragma unroll
            for (int j = 0; j < 2; j++) {
                int iy = wid * 256 + lid + (i * 2 + j) * 32;
                int ry = iy >> 3, qy = iy & 7;
                cp16(yb + (uint32_t)(ry * PADA + qy * 4) * 4u, gy + (size_t)ry * NN + qy * 4);
            }
        }
        CP_ARRIVE(sbu + SM_MBAR + st * 8);
    };

    load_chunk(0); load_chunk(1); load_chunk(2);

    uint32_t af[2][2][4], bf[2][8][2];             // double-buffered fragments

    auto ldA = [&](uint32_t base, int kb, int buf) {
#pragma unroll
        for (int mt = 0; mt < 2; mt++) {
            uint32_t ad = base + (uint32_t)((wm * 32 + mt * 16 + aR) * PADA + kb + aC) * 4u;
            LDSM_X4(af[buf][mt][0], af[buf][mt][1], af[buf][mt][2], af[buf][mt][3], ad);
        }
    };
    auto ldB = [&](uint32_t base, int kb, int buf) {
#pragma unroll
        for (int p = 0; p < 4; p++) {
            uint32_t bd = base + (uint32_t)((wn * 64 + p * 16 + bR) * PADA + kb + bC) * 4u;
            LDSM_X4(bf[buf][p * 2][0], bf[buf][p * 2][1],
                    bf[buf][p * 2 + 1][0], bf[buf][p * 2 + 1][1], bd);
        }
    };

    for (int c = 0; c < NCH; c++) {
        const int st = c & 3;
        // ---- consume-first: wait only on MY data ----
        MBAR_WAIT(sbu + SM_MBAR + st * 8, (c >> 2) & 1);
        const uint32_t aBase = sbu + (uint32_t)st * STAGE_B;
        const uint32_t yBase = aBase + ST_Y_OFF;

        ldA(aBase, 0, 0);  ldB(yBase, 0, 0);       // k8=0 frags
        ldA(aBase, 8, 1);  ldB(yBase, 8, 1);       // k8=1 frags
#pragma unroll
        for (int mt = 0; mt < 2; mt++)             // MMA k8=0
#pragma unroll
            for (int nt = 0; nt < 8; nt++)
                MMA_TF32(acc[mt][nt], af[0][mt], bf[0][nt]);

        // ---- mid-chunk prefetch: empty-wait now overlaps compute we already did;
        //      slower warps have had 1/4 chunk of slack to arrive ----
        if (c + 3 < NCH) {
            const int cc = c + 3, st3 = cc & 3;
            if (cc >= 4) MBAR_WAIT(sbu + SM_MBAR + 32 + st3 * 8, ((cc >> 2) - 1) & 1);
            load_chunk(cc);
        }

        ldA(aBase, 16, 0); ldB(yBase, 16, 0);      // k8=2 frags
#pragma unroll
        for (int mt = 0; mt < 2; mt++)             // MMA k8=1
#pragma unroll
            for (int nt = 0; nt < 8; nt++)
                MMA_TF32(acc[mt][nt], af[1][mt], bf[1][nt]);

        ldA(aBase, 24, 1); ldB(yBase, 24, 1);      // k8=3 frags
#pragma unroll
        for (int mt = 0; mt < 2; mt++)             // MMA k8=2
#pragma unroll
            for (int nt = 0; nt < 8; nt++)
                MMA_TF32(acc[mt][nt], af[0][mt], bf[0][nt]);

#pragma unroll
        for (int mt = 0; mt < 2; mt++)             // MMA k8=3
#pragma unroll
            for (int nt = 0; nt < 8; nt++)
                MMA_TF32(acc[mt][nt], af[1][mt], bf[1][nt]);

        if (lid == 0) MBAR_ARRIVE(sbu + SM_MBAR + 32 + st * 8);
    }

    // ---- epilogue: bias + LayerNorm + ReLU ----
    const float* sbias = sf + SM_PAR / 4;
    const float* sgam  = sbias + 128;
    const float* sbet  = sbias + 256;
    float* sred = sf + SM_RED / 4;

    float s1[2][2], s2[2][2];
#pragma unroll
    for (int mt = 0; mt < 2; mt++) { s1[mt][0] = s1[mt][1] = s2[mt][0] = s2[mt][1] = 0.f; }
#pragma unroll
    for (int mt = 0; mt < 2; mt++)
#pragma unroll
        for (int nt = 0; nt < 8; nt++) {
            int cc = wn * 64 + nt * 8 + 2 * tg;
            float b0 = sbias[cc], b1 = sbias[cc + 1];
            float v0 = acc[mt][nt][0] + b0, v1 = acc[mt][nt][1] + b1;
            float v2 = acc[mt][nt][2] + b0, v3 = acc[mt][nt][3] + b1;
            acc[mt][nt][0] = v0; acc[mt][nt][1] = v1;
            acc[mt][nt][2] = v2; acc[mt][nt][3] = v3;
            s1[mt][0] += v0 + v1;           s2[mt][0] += v0 * v0 + v1 * v1;
            s1[mt][1] += v2 + v3;           s2[mt][1] += v2 * v2 + v3 * v3;
        }
#pragma unroll
    for (int mt = 0; mt < 2; mt++)
#pragma unroll
        for (int h = 0; h < 2; h++) {
            s1[mt][h] += __shfl_xor_sync(0xffffffffu, s1[mt][h], 1);
            s1[mt][h] += __shfl_xor_sync(0xffffffffu, s1[mt][h], 2);
            s2[mt][h] += __shfl_xor_sync(0xffffffffu, s2[mt][h], 1);
            s2[mt][h] += __shfl_xor_sync(0xffffffffu, s2[mt][h], 2);
        }
    if (tg == 0) {
#pragma unroll
        for (int mt = 0; mt < 2; mt++)
#pragma unroll
            for (int h = 0; h < 2; h++) {
                int r = wm * 32 + mt * 16 + h * 8 + gp;
                sred[r * 4 + wn * 2 + 0] = s1[mt][h];
                sred[r * 4 + wn * 2 + 1] = s2[mt][h];
            }
    }
    __syncthreads();

    float* outBase = out + ((size_t)bt * NN + (size_t)rowTile * ROWS) * FF;
#pragma unroll
    for (int mt = 0; mt < 2; mt++)
#pragma unroll
        for (int h = 0; h < 2; h++) {
            int r = wm * 32 + mt * 16 + h * 8 + gp;
            float S1 = sred[r * 4 + 0] + sred[r * 4 + 2];
            float S2 = sred[r * 4 + 1] + sred[r * 4 + 3];
            float mean = S1 * (1.0f / 128.0f);
            float var  = S2 * (1.0f / 128.0f) - mean * mean;
            float inv  = rsqrtf(var + 1e-5f);
            float* orow = outBase + (size_t)r * FF;
#pragma unroll
            for (int nt = 0; nt < 8; nt++) {
                int cc = wn * 64 + nt * 8 + 2 * tg;
                float v0 = acc[mt][nt][h * 2 + 0];
                float v1 = acc[mt][nt][h * 2 + 1];
                float o0 = fmaxf((v0 - mean) * inv * sgam[cc]     + sbet[cc],     0.f);
                float o1 = fmaxf((v1 - mean) * inv * sgam[cc + 1] + sbet[cc + 1], 0.f);
                *(float2*)(orow + cc) = make_float2(o0, o1);
            }
        }
}

// ---------------- launch ----------------
extern "C" void kernel_launch(void* const* d_in, const int* in_sizes, int n_in,
                              void* d_out, int out_size) {
    const float* A     = (const float*)d_in[0];   // [8,2048,2048]
    const float* X     = (const float*)d_in[1];   // [8,2048,128]
    const float* W     = (const float*)d_in[2];   // [128,128]
    const float* bias  = (const float*)d_in[3];
    const float* gamma = (const float*)d_in[4];
    const float* beta  = (const float*)d_in[5];
    float* out = (float*)d_out;

    cudaFuncSetAttribute(y_kernel, cudaFuncAttributeMaxDynamicSharedMemorySize, SM_Y_TOTAL);
    cudaFuncSetAttribute(fused_kernel, cudaFuncAttributeMaxDynamicSharedMemorySize, SM_TOTAL);

    y_kernel<<<dim3(16, 8), 256, SM_Y_TOTAL>>>(X, W);
    fused_kernel<<<BATCH * (NN / ROWS), 128, SM_TOTAL>>>(A, bias, gamma, beta, out);
}

// round 16
// speedup vs baseline: 1.5003x; 1.0052x over previous
#include <cuda_runtime.h>
#include <cstdint>

// B=8, N=2048, F=D=128
//   H = A_hat@X ; O = H@W^T + b ; out = relu(LN(O)*gamma+beta)
// Re-associated:  Y = X@W^T (tiny) ;  O = A_hat@Y  ->  fused LN+ReLU epilogue.
//
// R15 = R14 + cross-chunk fragment pipelining:
//  - next chunk's k8=0 fragments loaded BEFORE this chunk's final MMA block
//    (full-wait is fast-path: data requested 3 chunks earlier)
//  - empty-arrive moved up to k8=2 (stage fully read once k8=3 frags are in regs)
//  - y_kernel split to 64-wide n-tiles (grid 256) to cut its runtime

#define BATCH 8
#define NN    2048
#define FF    128
#define ROWS  64
#define CK    32
#define NCH   64
#define PADA  36             // stage pitch (36 % 32 == 4 -> LDSM conflict-free)
#define PADW  132            // y_kernel tile pitch

#define ST_Y_OFF  9216       // A part 64*36*4
#define STAGE_B   27648      // + Y part 128*36*4 = 18432
#define SM_MBAR   110592     // full[4] @ +0, empty[4] @ +32
#define SM_PAR    110656     // bias|gamma|beta 3*512
#define SM_RED    112192     // 64 rows x 2 x {s1,s2} = 1024
#define SM_TOTAL  113216     // x2 CTAs = 226432

#define SM_Y_TOTAL 101376    // y_kernel: W 128*132*4 (67584) + X 64*132*4 (33792)

__device__ __align__(16) float g_Yt[BATCH * FF * NN];   // 8 MB scratch

__device__ __forceinline__ uint32_t smem_u32(const void* p) {
    uint32_t a;
    asm("{ .reg .u64 t; cvta.to.shared.u64 t, %1; cvt.u32.u64 %0, t; }" : "=r"(a) : "l"(p));
    return a;
}
__device__ __forceinline__ void cp16(uint32_t dst, const void* src) {
    asm volatile("cp.async.cg.shared.global [%0], [%1], 16;" :: "r"(dst), "l"(src) : "memory");
}

#define MBAR_INIT(mb, c)  asm volatile("mbarrier.init.shared.b64 [%0], %1;" :: "r"(mb), "r"(c) : "memory")
#define MBAR_ARRIVE(mb)   asm volatile("mbarrier.arrive.shared.b64 _, [%0];" :: "r"(mb) : "memory")
#define CP_ARRIVE(mb)     asm volatile("cp.async.mbarrier.arrive.noinc.shared::cta.b64 [%0];" :: "r"(mb) : "memory")

#define MBAR_WAIT(mb, ph) do {                                                     \
    uint32_t _m = (mb); uint32_t _p = (ph); uint32_t _d;                           \
    asm volatile("{\n\t.reg .pred p;\n\t"                                          \
        "mbarrier.try_wait.parity.acquire.cta.shared::cta.b64 p, [%1], %2;\n\t"    \
        "selp.b32 %0, 1, 0, p;\n\t}" : "=r"(_d) : "r"(_m), "r"(_p) : "memory");    \
    if (!_d) {                                                                     \
        asm volatile("{\n\t.reg .pred P1;\n\t"                                     \
        "W_%=:\n\t"                                                                \
        "mbarrier.try_wait.parity.acquire.cta.shared::cta.b64 P1, [%0], %1, 0x989680;\n\t" \
        "@P1 bra.uni D_%=;\n\tbra.uni W_%=;\n\tD_%=:\n\t}"                         \
        :: "r"(_m), "r"(_p) : "memory");                                           \
    }                                                                              \
} while (0)

#define LDSM_X4(r0, r1, r2, r3, addr)                                           \
    asm volatile("ldmatrix.sync.aligned.m8n8.x4.shared.b16 {%0,%1,%2,%3}, [%4];"\
        : "=r"(r0), "=r"(r1), "=r"(r2), "=r"(r3) : "r"(addr))

#define MMA_TF32(d, av, bv)                                                     \
    asm volatile("mma.sync.aligned.m16n8k8.row.col.f32.tf32.tf32.f32 "          \
        "{%0,%1,%2,%3}, {%4,%5,%6,%7}, {%8,%9}, {%0,%1,%2,%3};"                 \
        : "+f"((d)[0]), "+f"((d)[1]), "+f"((d)[2]), "+f"((d)[3])                \
        : "r"((av)[0]), "r"((av)[1]), "r"((av)[2]), "r"((av)[3]),               \
          "r"((bv)[0]), "r"((bv)[1]))

// ---------------- k0: Yt[b][d][n] = sum_f X[b][n][f] * W[d][f] ----------------
// grid (32 n-tiles of 64, 8 batches), 256 thr; warp tile 32(d) x 32(n)
__global__ __launch_bounds__(256, 1)
void y_kernel(const float* __restrict__ X, const float* __restrict__ W) {
    extern __shared__ char ysm[];
    float* sW = (float*)ysm;                         // [128][132]
    float* sX = (float*)(ysm + 67584);               // [64][132]
    const uint32_t wU = smem_u32(sW);
    const uint32_t xU = smem_u32(sX);

    const int tid = threadIdx.x;
    const int lid = tid & 31;
    const int wid = tid >> 5;
    const int wm  = wid >> 1, wn = wid & 1;          // wm 0..3 over d, wn 0..1 over n
    const int gp  = lid >> 2, tg = lid & 3;
    const int s   = lid >> 3, rr = lid & 7;
    const int aR = (s & 1) * 8 + rr, aC = (s >> 1) * 4;
    const int bR = (s >> 1) * 8 + rr, bC = (s & 1) * 4;

    const int n0 = blockIdx.x * 64;
    const int bt = blockIdx.y;
    const float* Xb = X + (size_t)bt * NN * FF + (size_t)n0 * FF;

#pragma unroll
    for (int i = 0; i < 16; i++) {                   // W: 4096 float4
        int id = tid + i * 256;
        int r = id >> 5, q = id & 31;
        *(float4*)(sW + r * PADW + q * 4) = *(const float4*)(W + (size_t)r * FF + q * 4);
    }
#pragma unroll
    for (int i = 0; i < 8; i++) {                    // X: 2048 float4
        int id = tid + i * 256;
        int r = id >> 5, q = id & 31;
        *(float4*)(sX + r * PADW + q * 4) = *(const float4*)(Xb + (size_t)r * FF + q * 4);
    }
    __syncthreads();

    float acc[2][4][4];
#pragma unroll
    for (int i = 0; i < 2; i++)
#pragma unroll
        for (int j = 0; j < 4; j++)
#pragma unroll
            for (int k = 0; k < 4; k++) acc[i][j][k] = 0.f;

#pragma unroll
    for (int k8 = 0; k8 < 16; k8++) {
        const int kb = k8 * 8;
        uint32_t af[2][4], bf[4][2];
#pragma unroll
        for (int mt = 0; mt < 2; mt++) {
            uint32_t ad = wU + (uint32_t)((wm * 32 + mt * 16 + aR) * PADW + kb + aC) * 4u;
            LDSM_X4(af[mt][0], af[mt][1], af[mt][2], af[mt][3], ad);
        }
#pragma unroll
        for (int p = 0; p < 2; p++) {
            uint32_t bd = xU + (uint32_t)((wn * 32 + p * 16 + bR) * PADW + kb + bC) * 4u;
            LDSM_X4(bf[p * 2][0], bf[p * 2][1], bf[p * 2 + 1][0], bf[p * 2 + 1][1], bd);
        }
#pragma unroll
        for (int mt = 0; mt < 2; mt++)
#pragma unroll
            for (int nt = 0; nt < 4; nt++)
                MMA_TF32(acc[mt][nt], af[mt], bf[nt]);
    }

    float* Yb = g_Yt + (size_t)bt * FF * NN;
#pragma unroll
    for (int mt = 0; mt < 2; mt++)
#pragma unroll
        for (int h = 0; h < 2; h++) {
            int d = wm * 32 + mt * 16 + h * 8 + gp;
#pragma unroll
            for (int nt = 0; nt < 4; nt++) {
                int n = n0 + wn * 32 + nt * 8 + 2 * tg;
                *(float2*)(Yb + (size_t)d * NN + n) =
                    make_float2(acc[mt][nt][h * 2 + 0], acc[mt][nt][h * 2 + 1]);
            }
        }
}

// ---------------- k1: fused O = A@Yt -> bias+LN+ReLU ----------------
__global__ __launch_bounds__(128, 2)
void fused_kernel(const float* __restrict__ A,
                  const float* __restrict__ bias, const float* __restrict__ gamma,
                  const float* __restrict__ beta, float* __restrict__ out) {
    extern __shared__ char smem[];
    float* sf = (float*)smem;
    const uint32_t sbu = smem_u32(smem);

    const int tid = threadIdx.x;
    const int lid = tid & 31;
    const int wid = tid >> 5;           // 0..3
    const int wm  = wid >> 1;           // rows half
    const int wn  = wid & 1;            // cols half
    const int gp  = lid >> 2, tg = lid & 3;
    const int s   = lid >> 3, rr = lid & 7;
    const int aR = (s & 1) * 8 + rr, aC = (s >> 1) * 4;
    const int bR = (s >> 1) * 8 + rr, bC = (s & 1) * 4;

    const int bt      = blockIdx.x >> 5;
    const int rowTile = blockIdx.x & 31;
    const float* Ab = A    + (size_t)bt * NN * NN + (size_t)rowTile * ROWS * NN;
    const float* Yb = g_Yt + (size_t)bt * FF * NN;

    if (tid == 0) {
#pragma unroll
        for (int st = 0; st < 4; st++) {
            MBAR_INIT(sbu + SM_MBAR + st * 8, 128);     // full: cp.async arrivals
            MBAR_INIT(sbu + SM_MBAR + 32 + st * 8, 4);  // empty: 4 warp arrivals
        }
    }
    sf[SM_PAR / 4 + tid]       = bias[tid];
    sf[SM_PAR / 4 + 128 + tid] = gamma[tid];
    sf[SM_PAR / 4 + 256 + tid] = beta[tid];
    __syncthreads();

    float acc[2][8][4];
#pragma unroll
    for (int i = 0; i < 2; i++)
#pragma unroll
        for (int j = 0; j < 8; j++)
#pragma unroll
            for (int k = 0; k < 4; k++) acc[i][j][k] = 0.f;

    auto load_chunk = [&](int c) {
        const int st = c & 3;
        const uint32_t ab = sbu + (uint32_t)st * STAGE_B;
        const uint32_t yb = ab + ST_Y_OFF;
        const float* ga = Ab + c * CK;
        const float* gy = Yb + c * CK;
#pragma unroll
        for (int i = 0; i < 4; i++) {
            int ia = wid * 128 + lid + i * 32;
            int ra = ia >> 3, qa = ia & 7;
            cp16(ab + (uint32_t)(ra * PADA + qa * 4) * 4u, ga + (size_t)ra * NN + qa * 4);
#pragma unroll
            for (int j = 0; j < 2; j++) {
                int iy = wid * 256 + lid + (i * 2 + j) * 32;
                int ry = iy >> 3, qy = iy & 7;
                cp16(yb + (uint32_t)(ry * PADA + qy * 4) * 4u, gy + (size_t)ry * NN + qy * 4);
            }
        }
        CP_ARRIVE(sbu + SM_MBAR + st * 8);
    };

    load_chunk(0); load_chunk(1); load_chunk(2);

    uint32_t af[2][2][4], bf[2][8][2];             // double-buffered fragments

    auto ldA = [&](uint32_t base, int kb, int buf) {
#pragma unroll
        for (int mt = 0; mt < 2; mt++) {
            uint32_t ad = base + (uint32_t)((wm * 32 + mt * 16 + aR) * PADA + kb + aC) * 4u;
            LDSM_X4(af[buf][mt][0], af[buf][mt][1], af[buf][mt][2], af[buf][mt][3], ad);
        }
    };
    auto ldB = [&](uint32_t base, int kb, int buf) {
#pragma unroll
        for (int p = 0; p < 4; p++) {
            uint32_t bd = base + (uint32_t)((wn * 64 + p * 16 + bR) * PADA + kb + bC) * 4u;
            LDSM_X4(bf[buf][p * 2][0], bf[buf][p * 2][1],
                    bf[buf][p * 2 + 1][0], bf[buf][p * 2 + 1][1], bd);
        }
    };

#define MMA_BLOCK(buf)                                                          \
    _Pragma("unroll")                                                           \
    for (int mt = 0; mt < 2; mt++)                                              \
        _Pragma("unroll")                                                       \
        for (int nt = 0; nt < 8; nt++)                                          \
            MMA_TF32(acc[mt][nt], af[buf][mt], bf[buf][nt]);

    // ---- prologue: wait chunk 0, load its k8=0 fragments into buf0 ----
    MBAR_WAIT(sbu + SM_MBAR + 0, 0);
    ldA(sbu, 0, 0); ldB(sbu + ST_Y_OFF, 0, 0);

    for (int c = 0; c < NCH; c++) {
        const int st = c & 3;
        const uint32_t aBase = sbu + (uint32_t)st * STAGE_B;
        const uint32_t yBase = aBase + ST_Y_OFF;
        // entering: frags (c, k8=0) in buf0
        // k8=0: load k8=1 frags -> buf1; MMA buf0
        ldA(aBase, 8, 1);  ldB(yBase, 8, 1);
        MMA_BLOCK(0)
        // k8=1: load k8=2 frags -> buf0; MMA buf1; then prefetch chunk c+3
        ldA(aBase, 16, 0); ldB(yBase, 16, 0);
        MMA_BLOCK(1)
        if (c + 3 < NCH) {
            const int cc = c + 3, st3 = cc & 3;
            if (cc >= 4) MBAR_WAIT(sbu + SM_MBAR + 32 + st3 * 8, ((cc >> 2) - 1) & 1);
            load_chunk(cc);
        }
        // k8=2: load k8=3 frags -> buf1 (last read of stage st) -> arrive empty; MMA buf0
        ldA(aBase, 24, 1); ldB(yBase, 24, 1);
        if (lid == 0) MBAR_ARRIVE(sbu + SM_MBAR + 32 + st * 8);
        MMA_BLOCK(0)
        // k8=3: wait full[c+1] (fast-path), load (c+1, k8=0) -> buf0; MMA buf1
        if (c + 1 < NCH) {
            const int cn = c + 1, stn = cn & 3;
            MBAR_WAIT(sbu + SM_MBAR + stn * 8, (cn >> 2) & 1);
            const uint32_t aN = sbu + (uint32_t)stn * STAGE_B;
            ldA(aN, 0, 0); ldB(aN + ST_Y_OFF, 0, 0);
        }
        MMA_BLOCK(1)
    }

    // ---- epilogue: bias + LayerNorm + ReLU ----
    const float* sbias = sf + SM_PAR / 4;
    const float* sgam  = sbias + 128;
    const float* sbet  = sbias + 256;
    float* sred = sf + SM_RED / 4;

    float s1[2][2], s2[2][2];
#pragma unroll
    for (int mt = 0; mt < 2; mt++) { s1[mt][0] = s1[mt][1] = s2[mt][0] = s2[mt][1] = 0.f; }
#pragma unroll
    for (int mt = 0; mt < 2; mt++)
#pragma unroll
        for (int nt = 0; nt < 8; nt++) {
            int cc = wn * 64 + nt * 8 + 2 * tg;
            float b0 = sbias[cc], b1 = sbias[cc + 1];
            float v0 = acc[mt][nt][0] + b0, v1 = acc[mt][nt][1] + b1;
            float v2 = acc[mt][nt][2] + b0, v3 = acc[mt][nt][3] + b1;
            acc[mt][nt][0] = v0; acc[mt][nt][1] = v1;
            acc[mt][nt][2] = v2; acc[mt][nt][3] = v3;
            s1[mt][0] += v0 + v1;           s2[mt][0] += v0 * v0 + v1 * v1;
            s1[mt][1] += v2 + v3;           s2[mt][1] += v2 * v2 + v3 * v3;
        }
#pragma unroll
    for (int mt = 0; mt < 2; mt++)
#pragma unroll
        for (int h = 0; h < 2; h++) {
            s1[mt][h] += __shfl_xor_sync(0xffffffffu, s1[mt][h], 1);
            s1[mt][h] += __shfl_xor_sync(0xffffffffu, s1[mt][h], 2);
            s2[mt][h] += __shfl_xor_sync(0xffffffffu, s2[mt][h], 1);
            s2[mt][h] += __shfl_xor_sync(0xffffffffu, s2[mt][h], 2);
        }
    if (tg == 0) {
#pragma unroll
        for (int mt = 0; mt < 2; mt++)
#pragma unroll
            for (int h = 0; h < 2; h++) {
                int r = wm * 32 + mt * 16 + h * 8 + gp;
                sred[r * 4 + wn * 2 + 0] = s1[mt][h];
                sred[r * 4 + wn * 2 + 1] = s2[mt][h];
            }
    }
    __syncthreads();

    float* outBase = out + ((size_t)bt * NN + (size_t)rowTile * ROWS) * FF;
#pragma unroll
    for (int mt = 0; mt < 2; mt++)
#pragma unroll
        for (int h = 0; h < 2; h++) {
            int r = wm * 32 + mt * 16 + h * 8 + gp;
            float S1 = sred[r * 4 + 0] + sred[r * 4 + 2];
            float S2 = sred[r * 4 + 1] + sred[r * 4 + 3];
            float mean = S1 * (1.0f / 128.0f);
            float var  = S2 * (1.0f / 128.0f) - mean * mean;
            float inv  = rsqrtf(var + 1e-5f);
            float* orow = outBase + (size_t)r * FF;
#pragma unroll
            for (int nt = 0; nt < 8; nt++) {
                int cc = wn * 64 + nt * 8 + 2 * tg;
                float v0 = acc[mt][nt][h * 2 + 0];
                float v1 = acc[mt][nt][h * 2 + 1];
                float o0 = fmaxf((v0 - mean) * inv * sgam[cc]     + sbet[cc],     0.f);
                float o1 = fmaxf((v1 - mean) * inv * sgam[cc + 1] + sbet[cc + 1], 0.f);
                *(float2*)(orow + cc) = make_float2(o0, o1);
            }
        }
}

// ---------------- launch ----------------
extern "C" void kernel_launch(void* const* d_in, const int* in_sizes, int n_in,
                              void* d_out, int out_size) {
    const float* A     = (const float*)d_in[0];   // [8,2048,2048]
    const float* X     = (const float*)d_in[1];   // [8,2048,128]
    const float* W     = (const float*)d_in[2];   // [128,128]
    const float* bias  = (const float*)d_in[3];
    const float* gamma = (const float*)d_in[4];
    const float* beta  = (const float*)d_in[5];
    float* out = (float*)d_out;

    cudaFuncSetAttribute(y_kernel, cudaFuncAttributeMaxDynamicSharedMemorySize, SM_Y_TOTAL);
    cudaFuncSetAttribute(fused_kernel, cudaFuncAttributeMaxDynamicSharedMemorySize, SM_TOTAL);

    y_kernel<<<dim3(NN / 64, BATCH), 256, SM_Y_TOTAL>>>(X, W);
    fused_kernel<<<BATCH * (NN / ROWS), 128, SM_TOTAL>>>(A, bias, gamma, beta, out);
}